// round 1
// baseline (speedup 1.0000x reference)
#include <cuda_runtime.h>
#include <math.h>

#define Mpts 16384
#define Dm   256
#define Hh   4
#define Kn   16
#define DFFm 1024

// ---------------- scratch (static device allocations are allowed) ----------
__device__ float g_x   [Mpts * Dm];    // running residual stream
__device__ float g_xn  [Mpts * Dm];    // layernorm output
__device__ float g_q   [Mpts * Dm];
__device__ float g_k   [Mpts * Dm];
__device__ float g_v   [Mpts * Dm];
__device__ float g_attn[Mpts * Dm];
__device__ float g_h   [Mpts * DFFm];

__device__ __forceinline__ float gelu_tanh(float x) {
    // jax.nn.gelu default (approximate=True)
    float x3 = x * x * x;
    return 0.5f * x * (1.0f + tanhf(0.7978845608028654f * (x + 0.044715f * x3)));
}

// ---------------- LayerNorm: one warp per 256-wide row ---------------------
__global__ void ln_kernel(const float* __restrict__ x, const float* __restrict__ g,
                          const float* __restrict__ b, float* __restrict__ y) {
    int row  = blockIdx.x * 8 + threadIdx.y;
    int lane = threadIdx.x;
    const float* xr = x + (size_t)row * Dm;
    float v[8];
    float s = 0.f;
#pragma unroll
    for (int j = 0; j < 8; j++) { v[j] = xr[lane + 32 * j]; s += v[j]; }
#pragma unroll
    for (int o = 16; o; o >>= 1) s += __shfl_xor_sync(0xffffffffu, s, o);
    float mean = s * (1.0f / Dm);
    float vs = 0.f;
#pragma unroll
    for (int j = 0; j < 8; j++) { float d = v[j] - mean; vs += d * d; }
#pragma unroll
    for (int o = 16; o; o >>= 1) vs += __shfl_xor_sync(0xffffffffu, vs, o);
    float inv = rsqrtf(vs * (1.0f / Dm) + 1e-5f);
    float* yr = y + (size_t)row * Dm;
#pragma unroll
    for (int j = 0; j < 8; j++) {
        int c = lane + 32 * j;
        yr[c] = (v[j] - mean) * inv * g[c] + b[c];
    }
}

// ---------------- fp32 tiled GEMM: C[M,N] = A[M,K] @ B[K,N] (+epilogue) ----
// EPI: 0 plain | 1 +res | 2 gelu(.+bias) | 3 +bias+res
#define BM 128
#define BN 128
#define BK 8
template <int EPI>
__global__ void gemm_kernel(const float* __restrict__ A, const float* __restrict__ B,
                            const float* __restrict__ bias, const float* res,
                            float* C, int N, int Kd) {
    __shared__ float As[BK][BM];
    __shared__ float Bs[BK][BN];
    const int tid = threadIdx.x;
    const int tx = tid & 15, ty = tid >> 4;
    const float* Ab = A + (size_t)blockIdx.y * BM * Kd;
    const float* Bb = B + blockIdx.x * BN;
    float acc[8][8] = {};
    const int aRow = tid >> 1, aCol = (tid & 1) * 4;
    const int bRow = tid >> 5, bCol = (tid & 31) * 4;

    for (int k0 = 0; k0 < Kd; k0 += BK) {
        float4 av = *(const float4*)(Ab + (size_t)aRow * Kd + k0 + aCol);
        As[aCol + 0][aRow] = av.x;
        As[aCol + 1][aRow] = av.y;
        As[aCol + 2][aRow] = av.z;
        As[aCol + 3][aRow] = av.w;
        float4 bv = *(const float4*)(Bb + (size_t)(k0 + bRow) * N + bCol);
        *(float4*)&Bs[bRow][bCol] = bv;
        __syncthreads();
#pragma unroll
        for (int k = 0; k < BK; k++) {
            float a[8], bb[8];
            *(float4*)(a)      = *(const float4*)&As[k][ty * 8];
            *(float4*)(a + 4)  = *(const float4*)&As[k][ty * 8 + 4];
            *(float4*)(bb)     = *(const float4*)&Bs[k][tx * 8];
            *(float4*)(bb + 4) = *(const float4*)&Bs[k][tx * 8 + 4];
#pragma unroll
            for (int i = 0; i < 8; i++)
#pragma unroll
                for (int j = 0; j < 8; j++) acc[i][j] = fmaf(a[i], bb[j], acc[i][j]);
        }
        __syncthreads();
    }

    int r0 = blockIdx.y * BM + ty * 8;
    int c0 = blockIdx.x * BN + tx * 8;
#pragma unroll
    for (int i = 0; i < 8; i++) {
        size_t off = (size_t)(r0 + i) * N + c0;
        float outv[8];
#pragma unroll
        for (int j = 0; j < 8; j++) {
            float vv = acc[i][j];
            if (EPI == 1) vv += res[off + j];
            if (EPI == 2) vv = gelu_tanh(vv + bias[c0 + j]);
            if (EPI == 3) vv += bias[c0 + j] + res[off + j];
            outv[j] = vv;
        }
        *(float4*)(C + off)     = *(float4*)(outv);
        *(float4*)(C + off + 4) = *(float4*)(outv + 4);
    }
}

// ---------------- KNN attention: one warp per query point ------------------
// lane handles 8 contiguous channels (c0 = lane*8) -> head = lane/8 (dh=64).
// Pass 1: scores from gathered K (+pe). Pass 2: weighted gather of V (+pe).
__global__ void attn_kernel(const float* __restrict__ q, const float* __restrict__ kall,
                            const float* __restrict__ vall,
                            const float* __restrict__ coord_q, const float* __restrict__ coord_c,
                            const int* __restrict__ idx,
                            const float* __restrict__ pe_w, const float* __restrict__ pe_b,
                            float* __restrict__ out) {
    __shared__ float s_pw[3 * Dm];
    __shared__ float s_pb[Dm];
    int tid = threadIdx.x;
    for (int i = tid; i < 3 * Dm; i += 256) s_pw[i] = pe_w[i];
    if (tid < Dm) s_pb[tid] = pe_b[tid];
    __syncthreads();

    int warp = tid >> 5, lane = tid & 31;
    int m  = blockIdx.x * 8 + warp;
    int c0 = lane * 8;

    float qv[8];
    {
        const float* qr = q + (size_t)m * Dm + c0;
        float4 a = *(const float4*)qr, b = *(const float4*)(qr + 4);
        qv[0] = a.x; qv[1] = a.y; qv[2] = a.z; qv[3] = a.w;
        qv[4] = b.x; qv[5] = b.y; qv[6] = b.z; qv[7] = b.w;
    }
    float cx = coord_q[m * 3 + 0], cy = coord_q[m * 3 + 1], cz = coord_q[m * 3 + 2];

    float pw0[8], pw1[8], pw2[8], pb[8];
#pragma unroll
    for (int j = 0; j < 8; j++) {
        int c = c0 + j;
        pw0[j] = s_pw[c]; pw1[j] = s_pw[Dm + c]; pw2[j] = s_pw[2 * Dm + c]; pb[j] = s_pb[c];
    }

    int ids[Kn];
#pragma unroll
    for (int kk = 0; kk < Kn; kk++) ids[kk] = idx[(size_t)m * Kn + kk];

    float sc[Kn];
#pragma unroll
    for (int kk = 0; kk < Kn; kk++) {
        int id = ids[kk];
        bool val = id >= 0;
        int ic = val ? id : 0;
        float rx = cx - coord_c[ic * 3 + 0];
        float ry = cy - coord_c[ic * 3 + 1];
        float rz = cz - coord_c[ic * 3 + 2];
        const float* kr = kall + (size_t)ic * Dm + c0;
        float4 a = *(const float4*)kr, b = *(const float4*)(kr + 4);
        float kv[8] = {a.x, a.y, a.z, a.w, b.x, b.y, b.z, b.w};
        float p = 0.f;
#pragma unroll
        for (int j = 0; j < 8; j++) {
            float pe = fmaf(rx, pw0[j], fmaf(ry, pw1[j], fmaf(rz, pw2[j], pb[j])));
            p = fmaf(qv[j], kv[j] + pe, p);
        }
        // reduce across the 8 lanes of this head group
        p += __shfl_xor_sync(0xffffffffu, p, 1);
        p += __shfl_xor_sync(0xffffffffu, p, 2);
        p += __shfl_xor_sync(0xffffffffu, p, 4);
        sc[kk] = val ? p * 0.125f : -1e9f;   // scale = 1/sqrt(64)
    }

    float mx = sc[0];
#pragma unroll
    for (int kk = 1; kk < Kn; kk++) mx = fmaxf(mx, sc[kk]);
    float sum = 0.f;
#pragma unroll
    for (int kk = 0; kk < Kn; kk++) { sc[kk] = expf(sc[kk] - mx); sum += sc[kk]; }
    float inv = 1.0f / sum;

    float acc[8] = {};
#pragma unroll
    for (int kk = 0; kk < Kn; kk++) {
        int id = ids[kk];
        int ic = id >= 0 ? id : 0;
        float rx = cx - coord_c[ic * 3 + 0];
        float ry = cy - coord_c[ic * 3 + 1];
        float rz = cz - coord_c[ic * 3 + 2];
        const float* vr = vall + (size_t)ic * Dm + c0;
        float4 a = *(const float4*)vr, b = *(const float4*)(vr + 4);
        float vv[8] = {a.x, a.y, a.z, a.w, b.x, b.y, b.z, b.w};
        float w = sc[kk];
#pragma unroll
        for (int j = 0; j < 8; j++) {
            float pe = fmaf(rx, pw0[j], fmaf(ry, pw1[j], fmaf(rz, pw2[j], pb[j])));
            acc[j] = fmaf(w, vv[j] + pe, acc[j]);
        }
    }
    float* orow = out + (size_t)m * Dm + c0;
    float4 o1 = {acc[0] * inv, acc[1] * inv, acc[2] * inv, acc[3] * inv};
    float4 o2 = {acc[4] * inv, acc[5] * inv, acc[6] * inv, acc[7] * inv};
    *(float4*)orow       = o1;
    *(float4*)(orow + 4) = o2;
}

// ---------------- driver ----------------------------------------------------
extern "C" void kernel_launch(void* const* d_in, const int* in_sizes, int n_in,
                              void* d_out, int out_size) {
    (void)in_sizes; (void)n_in; (void)out_size;
    const float* feat_a  = (const float*)d_in[0];
    const float* coord_a = (const float*)d_in[1];
    const float* feat_b  = (const float*)d_in[2];
    const float* coord_b = (const float*)d_in[3];
    const float* Wq      = (const float*)d_in[4];
    const float* Wk      = (const float*)d_in[5];
    const float* Wv      = (const float*)d_in[6];
    const float* Wo      = (const float*)d_in[7];
    const float* ln1_g   = (const float*)d_in[8];
    const float* ln1_b   = (const float*)d_in[9];
    const float* pe_w    = (const float*)d_in[10];
    const float* pe_b    = (const float*)d_in[11];
    const float* ffn_w1  = (const float*)d_in[12];
    const float* ffn_b1  = (const float*)d_in[13];
    const float* ffn_w2  = (const float*)d_in[14];
    const float* ffn_b2  = (const float*)d_in[15];
    const float* ln2_g   = (const float*)d_in[16];
    const float* ln2_b   = (const float*)d_in[17];
    const int*   knn_a2a = (const int*)d_in[18];
    const int*   knn_a2b = (const int*)d_in[19];
    float* out = (float*)d_out;

    float *x, *xn, *q, *k, *v, *attn, *h;
    cudaGetSymbolAddress((void**)&x,    g_x);
    cudaGetSymbolAddress((void**)&xn,   g_xn);
    cudaGetSymbolAddress((void**)&q,    g_q);
    cudaGetSymbolAddress((void**)&k,    g_k);
    cudaGetSymbolAddress((void**)&v,    g_v);
    cudaGetSymbolAddress((void**)&attn, g_attn);
    cudaGetSymbolAddress((void**)&h,    g_h);

    dim3 lnb(32, 8);
    dim3 gemmDD(Dm / BN, Mpts / BM);    // (2,128)
    dim3 gemmDF(DFFm / BN, Mpts / BM);  // (8,128)

    for (int blk = 0; blk < 2; blk++) {
        const float* xin = (blk == 0) ? feat_a : x;       // residual stream input
        const float* ctx = (blk == 0) ? feat_a : feat_b;  // K/V context (raw, un-normed)
        const float* cc  = (blk == 0) ? coord_a : coord_b;
        const int* idx   = (blk == 0) ? knn_a2a : knn_a2b;
        size_t wo  = (size_t)blk * Dm * Dm;

        // ln1 -> q ; k,v from raw ctx
        ln_kernel<<<Mpts / 8, lnb>>>(xin, ln1_g + blk * Dm, ln1_b + blk * Dm, xn);
        gemm_kernel<0><<<gemmDD, 256>>>(xn,  Wq + wo, nullptr, nullptr, q, Dm, Dm);
        gemm_kernel<0><<<gemmDD, 256>>>(ctx, Wk + wo, nullptr, nullptr, k, Dm, Dm);
        gemm_kernel<0><<<gemmDD, 256>>>(ctx, Wv + wo, nullptr, nullptr, v, Dm, Dm);

        // knn attention (pe gather fused)
        attn_kernel<<<Mpts / 8, 256>>>(q, k, v, coord_a, cc, idx,
                                       pe_w + (size_t)blk * 3 * Dm, pe_b + blk * Dm, attn);

        // x = xin + attn @ Wo
        gemm_kernel<1><<<gemmDD, 256>>>(attn, Wo + wo, nullptr, xin, x, Dm, Dm);

        // ffn
        ln_kernel<<<Mpts / 8, lnb>>>(x, ln2_g + blk * Dm, ln2_b + blk * Dm, xn);
        gemm_kernel<2><<<gemmDF, 256>>>(xn, ffn_w1 + (size_t)blk * Dm * DFFm,
                                        ffn_b1 + blk * DFFm, nullptr, h, DFFm, Dm);
        float* xo = (blk == 1) ? out : x;
        gemm_kernel<3><<<gemmDD, 256>>>(h, ffn_w2 + (size_t)blk * DFFm * Dm,
                                        ffn_b2 + blk * Dm, x, xo, Dm, DFFm);
    }
}

// round 2
// speedup vs baseline: 2.3446x; 2.3446x over previous
#include <cuda_runtime.h>
#include <math.h>

#define Mpts 16384
#define Dm   256
#define Hh   4
#define Kn   16
#define DFFm 1024

__device__ float g_x   [Mpts * Dm];
__device__ float g_xn  [Mpts * Dm];
__device__ float g_q   [Mpts * Dm];
__device__ float g_k   [Mpts * Dm];
__device__ float g_v   [Mpts * Dm];
__device__ float g_attn[Mpts * Dm];
__device__ float g_h   [Mpts * DFFm];

__device__ __forceinline__ float gelu_tanh(float x) {
    float x3 = x * x * x;
    return 0.5f * x * (1.0f + tanhf(0.7978845608028654f * (x + 0.044715f * x3)));
}

__device__ __forceinline__ unsigned f2tf(float f) {
    unsigned u;
    asm("cvt.rna.tf32.f32 %0, %1;" : "=r"(u) : "f"(f));
    return u;
}

__device__ __forceinline__ void mma_tf32(float c[4],
                                         unsigned a0, unsigned a1, unsigned a2, unsigned a3,
                                         unsigned b0, unsigned b1) {
    asm volatile(
        "mma.sync.aligned.m16n8k8.row.col.f32.tf32.tf32.f32 "
        "{%0,%1,%2,%3},{%4,%5,%6,%7},{%8,%9},{%0,%1,%2,%3};"
        : "+f"(c[0]), "+f"(c[1]), "+f"(c[2]), "+f"(c[3])
        : "r"(a0), "r"(a1), "r"(a2), "r"(a3), "r"(b0), "r"(b1));
}

// ---------------- LayerNorm: one warp per 256-wide row ---------------------
__global__ void ln_kernel(const float* __restrict__ x, const float* __restrict__ g,
                          const float* __restrict__ b, float* __restrict__ y) {
    int row  = blockIdx.x * 8 + threadIdx.y;
    int lane = threadIdx.x;
    const float* xr = x + (size_t)row * Dm;
    float v[8];
    float s = 0.f;
#pragma unroll
    for (int j = 0; j < 8; j++) { v[j] = xr[lane + 32 * j]; s += v[j]; }
#pragma unroll
    for (int o = 16; o; o >>= 1) s += __shfl_xor_sync(0xffffffffu, s, o);
    float mean = s * (1.0f / Dm);
    float vs = 0.f;
#pragma unroll
    for (int j = 0; j < 8; j++) { float d = v[j] - mean; vs += d * d; }
#pragma unroll
    for (int o = 16; o; o >>= 1) vs += __shfl_xor_sync(0xffffffffu, vs, o);
    float inv = rsqrtf(vs * (1.0f / Dm) + 1e-5f);
    float* yr = y + (size_t)row * Dm;
#pragma unroll
    for (int j = 0; j < 8; j++) {
        int c = lane + 32 * j;
        yr[c] = (v[j] - mean) * inv * g[c] + b[c];
    }
}

// ---------------- TF32 tensor-core GEMM: C = A[M,K] @ B[K,N] (+epilogue) ---
// CTA 128x128, BK=32, 8 warps (2 rows x 4 cols), warp tile 64x32 (mma m16n8k8)
// EPI: 0 plain | 1 +res | 2 gelu(.+bias) | 3 +bias+res
#define TBM 128
#define TBN 128
#define TBK 32
#define AST 36     /* As row stride (words): conflict-free frag loads        */
#define BST 136    /* Bs row stride (words): conflict-free frag loads        */

template <int EPI>
__global__ void __launch_bounds__(256, 1)
gemm_tf32(const float* __restrict__ A, const float* __restrict__ B,
          const float* __restrict__ bias, const float* __restrict__ res,
          float* __restrict__ C, int N, int Kd) {
    __shared__ unsigned As[TBM * AST];   // [row][k]  row stride 36
    __shared__ unsigned Bs[TBK * BST];   // [k][n]    row stride 136

    const int tid  = threadIdx.x;
    const int wid  = tid >> 5;
    const int lane = tid & 31;
    const int g    = lane >> 2;      // group id 0..7
    const int tig  = lane & 3;       // thread in group 0..3
    const int wRow = wid >> 2;       // 0..1 -> 64 rows each
    const int wCol = wid & 3;        // 0..3 -> 32 cols each
    const int rbase = wRow * 64;
    const int cbase = wCol * 32;

    const float* Ab = A + (size_t)blockIdx.y * TBM * Kd;
    const float* Bb = B + (size_t)blockIdx.x * TBN;

    // gmem load descriptors (4 float4 each for A and B per thread)
    int aRow[4], aK[4], bK[4], bN[4];
#pragma unroll
    for (int i = 0; i < 4; i++) {
        int li = i * 256 + tid;          // 0..1023
        aRow[i] = li >> 3;               // 0..127
        aK[i]   = (li & 7) * 4;          // 0..28
        bK[i]   = li >> 5;               // 0..31
        bN[i]   = (li & 31) * 4;         // 0..124
    }

    float acc[4][4][4] = {};             // [mt][nt][reg]

    const int nTiles = Kd / TBK;
    float4 pa[4], pb[4];
    // prefetch tile 0
#pragma unroll
    for (int i = 0; i < 4; i++) {
        pa[i] = *(const float4*)(Ab + (size_t)aRow[i] * Kd + aK[i]);
        pb[i] = *(const float4*)(Bb + (size_t)bK[i] * N + bN[i]);
    }

    for (int kt = 0; kt < nTiles; kt++) {
        // store current tile to smem (with RNA tf32 rounding)
#pragma unroll
        for (int i = 0; i < 4; i++) {
            unsigned* pA = &As[aRow[i] * AST + aK[i]];
            pA[0] = f2tf(pa[i].x); pA[1] = f2tf(pa[i].y);
            pA[2] = f2tf(pa[i].z); pA[3] = f2tf(pa[i].w);
            unsigned* pB = &Bs[bK[i] * BST + bN[i]];
            pB[0] = f2tf(pb[i].x); pB[1] = f2tf(pb[i].y);
            pB[2] = f2tf(pb[i].z); pB[3] = f2tf(pb[i].w);
        }
        __syncthreads();

        // prefetch next tile
        if (kt + 1 < nTiles) {
            int k0 = (kt + 1) * TBK;
#pragma unroll
            for (int i = 0; i < 4; i++) {
                pa[i] = *(const float4*)(Ab + (size_t)aRow[i] * Kd + k0 + aK[i]);
                pb[i] = *(const float4*)(Bb + (size_t)(k0 + bK[i]) * N + bN[i]);
            }
        }

        // compute: 4 k-steps of k8
#pragma unroll
        for (int ks = 0; ks < 4; ks++) {
            int kk = ks * 8;
            unsigned af[4][4], bf[4][2];
#pragma unroll
            for (int mt = 0; mt < 4; mt++) {
                const unsigned* p = &As[(rbase + mt * 16 + g) * AST + kk + tig];
                af[mt][0] = p[0];
                af[mt][1] = p[8 * AST];
                af[mt][2] = p[4];
                af[mt][3] = p[8 * AST + 4];
            }
#pragma unroll
            for (int nt = 0; nt < 4; nt++) {
                const unsigned* p = &Bs[(kk + tig) * BST + cbase + nt * 8 + g];
                bf[nt][0] = p[0];
                bf[nt][1] = p[4 * BST];
            }
#pragma unroll
            for (int mt = 0; mt < 4; mt++)
#pragma unroll
                for (int nt = 0; nt < 4; nt++)
                    mma_tf32(acc[mt][nt], af[mt][0], af[mt][1], af[mt][2], af[mt][3],
                             bf[nt][0], bf[nt][1]);
        }
        __syncthreads();
    }

    // epilogue: c0,c1 at (row, col..col+1); c2,c3 at (row+8, ...)
    const int gr0 = blockIdx.y * TBM + rbase + g;
    const int gc0 = blockIdx.x * TBN + cbase + 2 * tig;
#pragma unroll
    for (int mt = 0; mt < 4; mt++) {
#pragma unroll
        for (int half = 0; half < 2; half++) {
            int row = gr0 + mt * 16 + half * 8;
            size_t base = (size_t)row * N + gc0;
#pragma unroll
            for (int nt = 0; nt < 4; nt++) {
                size_t off = base + nt * 8;
                float v0 = acc[mt][nt][half * 2 + 0];
                float v1 = acc[mt][nt][half * 2 + 1];
                if (EPI == 1) {
                    float2 r = *(const float2*)(res + off);
                    v0 += r.x; v1 += r.y;
                } else if (EPI == 2) {
                    int c = gc0 + nt * 8;
                    v0 = gelu_tanh(v0 + bias[c]);
                    v1 = gelu_tanh(v1 + bias[c + 1]);
                } else if (EPI == 3) {
                    int c = gc0 + nt * 8;
                    float2 r = *(const float2*)(res + off);
                    v0 += bias[c] + r.x;
                    v1 += bias[c + 1] + r.y;
                }
                float2 o = {v0, v1};
                *(float2*)(C + off) = o;
            }
        }
    }
}

// ---------------- KNN attention: one warp per query point ------------------
__global__ void attn_kernel(const float* __restrict__ q, const float* __restrict__ kall,
                            const float* __restrict__ vall,
                            const float* __restrict__ coord_q, const float* __restrict__ coord_c,
                            const int* __restrict__ idx,
                            const float* __restrict__ pe_w, const float* __restrict__ pe_b,
                            float* __restrict__ out) {
    __shared__ float s_pw[3 * Dm];
    __shared__ float s_pb[Dm];
    int tid = threadIdx.x;
    for (int i = tid; i < 3 * Dm; i += 256) s_pw[i] = pe_w[i];
    if (tid < Dm) s_pb[tid] = pe_b[tid];
    __syncthreads();

    int warp = tid >> 5, lane = tid & 31;
    int m  = blockIdx.x * 8 + warp;
    int c0 = lane * 8;

    float qv[8];
    {
        const float* qr = q + (size_t)m * Dm + c0;
        float4 a = *(const float4*)qr, b = *(const float4*)(qr + 4);
        qv[0] = a.x; qv[1] = a.y; qv[2] = a.z; qv[3] = a.w;
        qv[4] = b.x; qv[5] = b.y; qv[6] = b.z; qv[7] = b.w;
    }
    float cx = coord_q[m * 3 + 0], cy = coord_q[m * 3 + 1], cz = coord_q[m * 3 + 2];

    float pw0[8], pw1[8], pw2[8], pb[8];
#pragma unroll
    for (int j = 0; j < 8; j++) {
        int c = c0 + j;
        pw0[j] = s_pw[c]; pw1[j] = s_pw[Dm + c]; pw2[j] = s_pw[2 * Dm + c]; pb[j] = s_pb[c];
    }

    int ids[Kn];
#pragma unroll
    for (int kk = 0; kk < Kn; kk++) ids[kk] = idx[(size_t)m * Kn + kk];

    float sc[Kn];
#pragma unroll
    for (int kk = 0; kk < Kn; kk++) {
        int id = ids[kk];
        bool val = id >= 0;
        int ic = val ? id : 0;
        float rx = cx - coord_c[ic * 3 + 0];
        float ry = cy - coord_c[ic * 3 + 1];
        float rz = cz - coord_c[ic * 3 + 2];
        const float* kr = kall + (size_t)ic * Dm + c0;
        float4 a = *(const float4*)kr, b = *(const float4*)(kr + 4);
        float kv[8] = {a.x, a.y, a.z, a.w, b.x, b.y, b.z, b.w};
        float p = 0.f;
#pragma unroll
        for (int j = 0; j < 8; j++) {
            float pe = fmaf(rx, pw0[j], fmaf(ry, pw1[j], fmaf(rz, pw2[j], pb[j])));
            p = fmaf(qv[j], kv[j] + pe, p);
        }
        p += __shfl_xor_sync(0xffffffffu, p, 1);
        p += __shfl_xor_sync(0xffffffffu, p, 2);
        p += __shfl_xor_sync(0xffffffffu, p, 4);
        sc[kk] = val ? p * 0.125f : -1e9f;
    }

    float mx = sc[0];
#pragma unroll
    for (int kk = 1; kk < Kn; kk++) mx = fmaxf(mx, sc[kk]);
    float sum = 0.f;
#pragma unroll
    for (int kk = 0; kk < Kn; kk++) { sc[kk] = expf(sc[kk] - mx); sum += sc[kk]; }
    float inv = 1.0f / sum;

    float acc[8] = {};
#pragma unroll
    for (int kk = 0; kk < Kn; kk++) {
        int id = ids[kk];
        int ic = id >= 0 ? id : 0;
        float rx = cx - coord_c[ic * 3 + 0];
        float ry = cy - coord_c[ic * 3 + 1];
        float rz = cz - coord_c[ic * 3 + 2];
        const float* vr = vall + (size_t)ic * Dm + c0;
        float4 a = *(const float4*)vr, b = *(const float4*)(vr + 4);
        float vv[8] = {a.x, a.y, a.z, a.w, b.x, b.y, b.z, b.w};
        float w = sc[kk];
#pragma unroll
        for (int j = 0; j < 8; j++) {
            float pe = fmaf(rx, pw0[j], fmaf(ry, pw1[j], fmaf(rz, pw2[j], pb[j])));
            acc[j] = fmaf(w, vv[j] + pe, acc[j]);
        }
    }
    float* orow = out + (size_t)m * Dm + c0;
    float4 o1 = {acc[0] * inv, acc[1] * inv, acc[2] * inv, acc[3] * inv};
    float4 o2 = {acc[4] * inv, acc[5] * inv, acc[6] * inv, acc[7] * inv};
    *(float4*)orow       = o1;
    *(float4*)(orow + 4) = o2;
}

// ---------------- driver ----------------------------------------------------
extern "C" void kernel_launch(void* const* d_in, const int* in_sizes, int n_in,
                              void* d_out, int out_size) {
    (void)in_sizes; (void)n_in; (void)out_size;
    const float* feat_a  = (const float*)d_in[0];
    const float* coord_a = (const float*)d_in[1];
    const float* feat_b  = (const float*)d_in[2];
    const float* coord_b = (const float*)d_in[3];
    const float* Wq      = (const float*)d_in[4];
    const float* Wk      = (const float*)d_in[5];
    const float* Wv      = (const float*)d_in[6];
    const float* Wo      = (const float*)d_in[7];
    const float* ln1_g   = (const float*)d_in[8];
    const float* ln1_b   = (const float*)d_in[9];
    const float* pe_w    = (const float*)d_in[10];
    const float* pe_b    = (const float*)d_in[11];
    const float* ffn_w1  = (const float*)d_in[12];
    const float* ffn_b1  = (const float*)d_in[13];
    const float* ffn_w2  = (const float*)d_in[14];
    const float* ffn_b2  = (const float*)d_in[15];
    const float* ln2_g   = (const float*)d_in[16];
    const float* ln2_b   = (const float*)d_in[17];
    const int*   knn_a2a = (const int*)d_in[18];
    const int*   knn_a2b = (const int*)d_in[19];
    float* out = (float*)d_out;

    float *x, *xn, *q, *k, *v, *attn, *h;
    cudaGetSymbolAddress((void**)&x,    g_x);
    cudaGetSymbolAddress((void**)&xn,   g_xn);
    cudaGetSymbolAddress((void**)&q,    g_q);
    cudaGetSymbolAddress((void**)&k,    g_k);
    cudaGetSymbolAddress((void**)&v,    g_v);
    cudaGetSymbolAddress((void**)&attn, g_attn);
    cudaGetSymbolAddress((void**)&h,    g_h);

    dim3 lnb(32, 8);
    dim3 gemmDD(Dm / TBN, Mpts / TBM);    // (2,128)
    dim3 gemmDF(DFFm / TBN, Mpts / TBM);  // (8,128)

    for (int blk = 0; blk < 2; blk++) {
        const float* xin = (blk == 0) ? feat_a : x;
        const float* ctx = (blk == 0) ? feat_a : feat_b;
        const float* cc  = (blk == 0) ? coord_a : coord_b;
        const int* idx   = (blk == 0) ? knn_a2a : knn_a2b;
        size_t wo  = (size_t)blk * Dm * Dm;

        ln_kernel<<<Mpts / 8, lnb>>>(xin, ln1_g + blk * Dm, ln1_b + blk * Dm, xn);
        gemm_tf32<0><<<gemmDD, 256>>>(xn,  Wq + wo, nullptr, nullptr, q, Dm, Dm);
        gemm_tf32<0><<<gemmDD, 256>>>(ctx, Wk + wo, nullptr, nullptr, k, Dm, Dm);
        gemm_tf32<0><<<gemmDD, 256>>>(ctx, Wv + wo, nullptr, nullptr, v, Dm, Dm);

        attn_kernel<<<Mpts / 8, 256>>>(q, k, v, coord_a, cc, idx,
                                       pe_w + (size_t)blk * 3 * Dm, pe_b + blk * Dm, attn);

        gemm_tf32<1><<<gemmDD, 256>>>(attn, Wo + wo, nullptr, xin, x, Dm, Dm);

        ln_kernel<<<Mpts / 8, lnb>>>(x, ln2_g + blk * Dm, ln2_b + blk * Dm, xn);
        gemm_tf32<2><<<gemmDF, 256>>>(xn, ffn_w1 + (size_t)blk * Dm * DFFm,
                                      ffn_b1 + blk * DFFm, nullptr, h, DFFm, Dm);
        float* xo = (blk == 1) ? out : x;
        gemm_tf32<3><<<gemmDD, 256>>>(h, ffn_w2 + (size_t)blk * DFFm * Dm,
                                      ffn_b2 + blk * Dm, x, xo, Dm, DFFm);
    }
}

// round 3
// speedup vs baseline: 2.4150x; 1.0300x over previous
#include <cuda_runtime.h>
#include <math.h>

#define Mpts 16384
#define Dm   256
#define Kn   16
#define DFFm 1024

#define STAGES 3
#define TBM 128
#define TBN 128
#define TBK 32
#define AST 36     /* As row stride (words) */
#define BST 136    /* Bs row stride (words) */
#define GEMM_SMEM (STAGES * (TBM * AST + TBK * BST) * 4)

// ---------------- scratch -----------------------------------------------
__device__ float g_x   [Mpts * Dm];
__device__ float g_xn  [Mpts * Dm];     // tf32-rounded LN output
__device__ float g_q   [Mpts * Dm];
__device__ float g_k   [Mpts * Dm];
__device__ float g_v   [Mpts * Dm];
__device__ float g_attn[Mpts * Dm];     // tf32-rounded attention output
__device__ float g_h   [Mpts * DFFm];   // tf32-rounded gelu output
__device__ float g_fa  [Mpts * Dm];     // tf32-rounded feat_a
__device__ float g_fb  [Mpts * Dm];     // tf32-rounded feat_b
__device__ float g_wq  [2 * Dm * Dm];
__device__ float g_wk  [2 * Dm * Dm];
__device__ float g_wv  [2 * Dm * Dm];
__device__ float g_wo  [2 * Dm * Dm];
__device__ float g_w1  [2 * Dm * DFFm];
__device__ float g_w2  [2 * DFFm * Dm];

__device__ __forceinline__ float gelu_tanh(float x) {
    float x3 = x * x * x;
    return 0.5f * x * (1.0f + tanhf(0.7978845608028654f * (x + 0.044715f * x3)));
}

__device__ __forceinline__ unsigned f2tf(float f) {
    unsigned u;
    asm("cvt.rna.tf32.f32 %0, %1;" : "=r"(u) : "f"(f));
    return u;
}
__device__ __forceinline__ float rndtf(float f) { return __uint_as_float(f2tf(f)); }

__device__ __forceinline__ void mma_tf32(float c[4],
                                         unsigned a0, unsigned a1, unsigned a2, unsigned a3,
                                         unsigned b0, unsigned b1) {
    asm volatile(
        "mma.sync.aligned.m16n8k8.row.col.f32.tf32.tf32.f32 "
        "{%0,%1,%2,%3},{%4,%5,%6,%7},{%8,%9},{%0,%1,%2,%3};"
        : "+f"(c[0]), "+f"(c[1]), "+f"(c[2]), "+f"(c[3])
        : "r"(a0), "r"(a1), "r"(a2), "r"(a3), "r"(b0), "r"(b1));
}

__device__ __forceinline__ void cp16(void* s, const void* g) {
    unsigned a = (unsigned)__cvta_generic_to_shared(s);
    asm volatile("cp.async.cg.shared.global [%0], [%1], 16;" :: "r"(a), "l"(g));
}

// ---------------- elementwise tf32 rounding ------------------------------
__global__ void rnd_kernel(const float* __restrict__ x, float* __restrict__ y, int n4) {
    int i = blockIdx.x * 256 + threadIdx.x;
    if (i < n4) {
        float4 v = ((const float4*)x)[i];
        float4 o = {rndtf(v.x), rndtf(v.y), rndtf(v.z), rndtf(v.w)};
        ((float4*)y)[i] = o;
    }
}

// ---------------- LayerNorm (tf32-rounded output) ------------------------
__global__ void ln_kernel(const float* __restrict__ x, const float* __restrict__ g,
                          const float* __restrict__ b, float* __restrict__ y) {
    int row  = blockIdx.x * 8 + threadIdx.y;
    int lane = threadIdx.x;
    const float* xr = x + (size_t)row * Dm;
    float v[8];
    float s = 0.f;
#pragma unroll
    for (int j = 0; j < 8; j++) { v[j] = xr[lane + 32 * j]; s += v[j]; }
#pragma unroll
    for (int o = 16; o; o >>= 1) s += __shfl_xor_sync(0xffffffffu, s, o);
    float mean = s * (1.0f / Dm);
    float vs = 0.f;
#pragma unroll
    for (int j = 0; j < 8; j++) { float d = v[j] - mean; vs += d * d; }
#pragma unroll
    for (int o = 16; o; o >>= 1) vs += __shfl_xor_sync(0xffffffffu, vs, o);
    float inv = rsqrtf(vs * (1.0f / Dm) + 1e-5f);
    float* yr = y + (size_t)row * Dm;
#pragma unroll
    for (int j = 0; j < 8; j++) {
        int c = lane + 32 * j;
        yr[c] = rndtf((v[j] - mean) * inv * g[c] + b[c]);
    }
}

// ---------------- TF32 GEMM, 3-stage cp.async pipeline -------------------
// Inputs A,B are pre-rounded to tf32 bit patterns. EPI: 0 plain | 1 +res |
// 2 gelu(.+bias) tf32-rounded out | 3 +bias+res
template <int EPI>
__global__ void __launch_bounds__(256, 1)
gemm_tf32(const float* __restrict__ A, const float* __restrict__ B,
          const float* __restrict__ bias, const float* __restrict__ res,
          float* __restrict__ C, int N, int Kd) {
    extern __shared__ unsigned smem[];
    unsigned* As = smem;                         // [STAGES][TBM][AST]
    unsigned* Bs = smem + STAGES * TBM * AST;    // [STAGES][TBK][BST]

    const int tid  = threadIdx.x;
    const int wid  = tid >> 5;
    const int lane = tid & 31;
    const int g    = lane >> 2;
    const int tig  = lane & 3;
    const int rbase = (wid >> 2) * 64;
    const int cbase = (wid & 3) * 32;

    const float* Ab = A + (size_t)blockIdx.y * TBM * Kd;
    const float* Bb = B + (size_t)blockIdx.x * TBN;

    int aRow[4], aCol[4], bRow[4], bCol[4];
#pragma unroll
    for (int i = 0; i < 4; i++) {
        int c = i * 256 + tid;
        aRow[i] = c >> 3;  aCol[i] = (c & 7) * 4;
        bRow[i] = c >> 5;  bCol[i] = (c & 31) * 4;
    }

    const int nT = Kd / TBK;

#define ISSUE(s, k0)                                                          \
    {                                                                         \
        unsigned* Asb = As + (s) * TBM * AST;                                 \
        unsigned* Bsb = Bs + (s) * TBK * BST;                                 \
        _Pragma("unroll")                                                     \
        for (int i = 0; i < 4; i++) {                                         \
            cp16(&Asb[aRow[i] * AST + aCol[i]],                               \
                 Ab + (size_t)aRow[i] * Kd + (k0) + aCol[i]);                 \
            cp16(&Bsb[bRow[i] * BST + bCol[i]],                               \
                 Bb + (size_t)((k0) + bRow[i]) * N + bCol[i]);                \
        }                                                                     \
    }

    ISSUE(0, 0);
    asm volatile("cp.async.commit_group;");
    ISSUE(1, TBK);
    asm volatile("cp.async.commit_group;");

    float acc[4][4][4] = {};

    for (int kt = 0; kt < nT; kt++) {
        asm volatile("cp.async.wait_group 1;");
        __syncthreads();
        int nk = kt + 2;
        if (nk < nT) {
            int s = nk % STAGES;
            ISSUE(s, nk * TBK);
        }
        asm volatile("cp.async.commit_group;");

        const unsigned* Asb = As + (kt % STAGES) * TBM * AST;
        const unsigned* Bsb = Bs + (kt % STAGES) * TBK * BST;
#pragma unroll
        for (int ks = 0; ks < 4; ks++) {
            int kk = ks * 8;
            unsigned af[4][4], bf[4][2];
#pragma unroll
            for (int mt = 0; mt < 4; mt++) {
                const unsigned* p = &Asb[(rbase + mt * 16 + g) * AST + kk + tig];
                af[mt][0] = p[0];
                af[mt][1] = p[8 * AST];
                af[mt][2] = p[4];
                af[mt][3] = p[8 * AST + 4];
            }
#pragma unroll
            for (int nt = 0; nt < 4; nt++) {
                const unsigned* p = &Bsb[(kk + tig) * BST + cbase + nt * 8 + g];
                bf[nt][0] = p[0];
                bf[nt][1] = p[4 * BST];
            }
#pragma unroll
            for (int mt = 0; mt < 4; mt++)
#pragma unroll
                for (int nt = 0; nt < 4; nt++)
                    mma_tf32(acc[mt][nt], af[mt][0], af[mt][1], af[mt][2], af[mt][3],
                             bf[nt][0], bf[nt][1]);
        }
        __syncthreads();
    }
#undef ISSUE

    const int gr0 = blockIdx.y * TBM + rbase + g;
    const int gc0 = blockIdx.x * TBN + cbase + 2 * tig;
#pragma unroll
    for (int mt = 0; mt < 4; mt++) {
#pragma unroll
        for (int half = 0; half < 2; half++) {
            int row = gr0 + mt * 16 + half * 8;
            size_t base = (size_t)row * N + gc0;
#pragma unroll
            for (int nt = 0; nt < 4; nt++) {
                size_t off = base + nt * 8;
                float v0 = acc[mt][nt][half * 2 + 0];
                float v1 = acc[mt][nt][half * 2 + 1];
                if (EPI == 1) {
                    float2 r = *(const float2*)(res + off);
                    v0 += r.x; v1 += r.y;
                } else if (EPI == 2) {
                    int c = gc0 + nt * 8;
                    v0 = rndtf(gelu_tanh(v0 + bias[c]));
                    v1 = rndtf(gelu_tanh(v1 + bias[c + 1]));
                } else if (EPI == 3) {
                    int c = gc0 + nt * 8;
                    float2 r = *(const float2*)(res + off);
                    v0 += bias[c] + r.x;
                    v1 += bias[c + 1] + r.y;
                }
                float2 o = {v0, v1};
                *(float2*)(C + off) = o;
            }
        }
    }
}

// ---------------- KNN attention (tf32-rounded output) --------------------
__global__ void attn_kernel(const float* __restrict__ q, const float* __restrict__ kall,
                            const float* __restrict__ vall,
                            const float* __restrict__ coord_q, const float* __restrict__ coord_c,
                            const int* __restrict__ idx,
                            const float* __restrict__ pe_w, const float* __restrict__ pe_b,
                            float* __restrict__ out) {
    __shared__ float s_pw[3 * Dm];
    __shared__ float s_pb[Dm];
    int tid = threadIdx.x;
    for (int i = tid; i < 3 * Dm; i += 256) s_pw[i] = pe_w[i];
    if (tid < Dm) s_pb[tid] = pe_b[tid];
    __syncthreads();

    int warp = tid >> 5, lane = tid & 31;
    int m  = blockIdx.x * 8 + warp;
    int c0 = lane * 8;

    float qv[8];
    {
        const float* qr = q + (size_t)m * Dm + c0;
        float4 a = *(const float4*)qr, b = *(const float4*)(qr + 4);
        qv[0] = a.x; qv[1] = a.y; qv[2] = a.z; qv[3] = a.w;
        qv[4] = b.x; qv[5] = b.y; qv[6] = b.z; qv[7] = b.w;
    }
    float cx = coord_q[m * 3 + 0], cy = coord_q[m * 3 + 1], cz = coord_q[m * 3 + 2];

    float pw0[8], pw1[8], pw2[8], pb[8];
#pragma unroll
    for (int j = 0; j < 8; j++) {
        int c = c0 + j;
        pw0[j] = s_pw[c]; pw1[j] = s_pw[Dm + c]; pw2[j] = s_pw[2 * Dm + c]; pb[j] = s_pb[c];
    }

    int ids[Kn];
#pragma unroll
    for (int kk = 0; kk < Kn; kk++) ids[kk] = idx[(size_t)m * Kn + kk];

    float sc[Kn];
#pragma unroll
    for (int kk = 0; kk < Kn; kk++) {
        int id = ids[kk];
        bool val = id >= 0;
        int ic = val ? id : 0;
        float rx = cx - coord_c[ic * 3 + 0];
        float ry = cy - coord_c[ic * 3 + 1];
        float rz = cz - coord_c[ic * 3 + 2];
        const float* kr = kall + (size_t)ic * Dm + c0;
        float4 a = *(const float4*)kr, b = *(const float4*)(kr + 4);
        float kv[8] = {a.x, a.y, a.z, a.w, b.x, b.y, b.z, b.w};
        float p = 0.f;
#pragma unroll
        for (int j = 0; j < 8; j++) {
            float pe = fmaf(rx, pw0[j], fmaf(ry, pw1[j], fmaf(rz, pw2[j], pb[j])));
            p = fmaf(qv[j], kv[j] + pe, p);
        }
        p += __shfl_xor_sync(0xffffffffu, p, 1);
        p += __shfl_xor_sync(0xffffffffu, p, 2);
        p += __shfl_xor_sync(0xffffffffu, p, 4);
        sc[kk] = val ? p * 0.125f : -1e9f;
    }

    float mx = sc[0];
#pragma unroll
    for (int kk = 1; kk < Kn; kk++) mx = fmaxf(mx, sc[kk]);
    float sum = 0.f;
#pragma unroll
    for (int kk = 0; kk < Kn; kk++) { sc[kk] = expf(sc[kk] - mx); sum += sc[kk]; }
    float inv = 1.0f / sum;

    float acc[8] = {};
#pragma unroll
    for (int kk = 0; kk < Kn; kk++) {
        int id = ids[kk];
        int ic = id >= 0 ? id : 0;
        float rx = cx - coord_c[ic * 3 + 0];
        float ry = cy - coord_c[ic * 3 + 1];
        float rz = cz - coord_c[ic * 3 + 2];
        const float* vr = vall + (size_t)ic * Dm + c0;
        float4 a = *(const float4*)vr, b = *(const float4*)(vr + 4);
        float vv[8] = {a.x, a.y, a.z, a.w, b.x, b.y, b.z, b.w};
        float w = sc[kk];
#pragma unroll
        for (int j = 0; j < 8; j++) {
            float pe = fmaf(rx, pw0[j], fmaf(ry, pw1[j], fmaf(rz, pw2[j], pb[j])));
            acc[j] = fmaf(w, vv[j] + pe, acc[j]);
        }
    }
    float* orow = out + (size_t)m * Dm + c0;
    float4 o1 = {rndtf(acc[0] * inv), rndtf(acc[1] * inv), rndtf(acc[2] * inv), rndtf(acc[3] * inv)};
    float4 o2 = {rndtf(acc[4] * inv), rndtf(acc[5] * inv), rndtf(acc[6] * inv), rndtf(acc[7] * inv)};
    *(float4*)orow       = o1;
    *(float4*)(orow + 4) = o2;
}

// ---------------- driver --------------------------------------------------
extern "C" void kernel_launch(void* const* d_in, const int* in_sizes, int n_in,
                              void* d_out, int out_size) {
    (void)in_sizes; (void)n_in; (void)out_size;
    const float* feat_a  = (const float*)d_in[0];
    const float* coord_a = (const float*)d_in[1];
    const float* feat_b  = (const float*)d_in[2];
    const float* coord_b = (const float*)d_in[3];
    const float* Wq      = (const float*)d_in[4];
    const float* Wk      = (const float*)d_in[5];
    const float* Wv      = (const float*)d_in[6];
    const float* Wo      = (const float*)d_in[7];
    const float* ln1_g   = (const float*)d_in[8];
    const float* ln1_b   = (const float*)d_in[9];
    const float* pe_w    = (const float*)d_in[10];
    const float* pe_b    = (const float*)d_in[11];
    const float* ffn_w1  = (const float*)d_in[12];
    const float* ffn_b1  = (const float*)d_in[13];
    const float* ffn_w2  = (const float*)d_in[14];
    const float* ffn_b2  = (const float*)d_in[15];
    const float* ln2_g   = (const float*)d_in[16];
    const float* ln2_b   = (const float*)d_in[17];
    const int*   knn_a2a = (const int*)d_in[18];
    const int*   knn_a2b = (const int*)d_in[19];
    float* out = (float*)d_out;

    float *x, *xn, *q, *k, *v, *attn, *h, *fa, *fb, *wq, *wk, *wv, *wo, *w1, *w2;
    cudaGetSymbolAddress((void**)&x,    g_x);
    cudaGetSymbolAddress((void**)&xn,   g_xn);
    cudaGetSymbolAddress((void**)&q,    g_q);
    cudaGetSymbolAddress((void**)&k,    g_k);
    cudaGetSymbolAddress((void**)&v,    g_v);
    cudaGetSymbolAddress((void**)&attn, g_attn);
    cudaGetSymbolAddress((void**)&h,    g_h);
    cudaGetSymbolAddress((void**)&fa,   g_fa);
    cudaGetSymbolAddress((void**)&fb,   g_fb);
    cudaGetSymbolAddress((void**)&wq,   g_wq);
    cudaGetSymbolAddress((void**)&wk,   g_wk);
    cudaGetSymbolAddress((void**)&wv,   g_wv);
    cudaGetSymbolAddress((void**)&wo,   g_wo);
    cudaGetSymbolAddress((void**)&w1,   g_w1);
    cudaGetSymbolAddress((void**)&w2,   g_w2);

    static bool attr_done = false;
    if (!attr_done) {
        cudaFuncSetAttribute(gemm_tf32<0>, cudaFuncAttributeMaxDynamicSharedMemorySize, GEMM_SMEM);
        cudaFuncSetAttribute(gemm_tf32<1>, cudaFuncAttributeMaxDynamicSharedMemorySize, GEMM_SMEM);
        cudaFuncSetAttribute(gemm_tf32<2>, cudaFuncAttributeMaxDynamicSharedMemorySize, GEMM_SMEM);
        cudaFuncSetAttribute(gemm_tf32<3>, cudaFuncAttributeMaxDynamicSharedMemorySize, GEMM_SMEM);
        attr_done = true;
    }

    // pre-round all GEMM operands to tf32 bit patterns
    rnd_kernel<<<Mpts * Dm / 1024, 256>>>(feat_a, fa, Mpts * Dm / 4);
    rnd_kernel<<<Mpts * Dm / 1024, 256>>>(feat_b, fb, Mpts * Dm / 4);
    rnd_kernel<<<2 * Dm * Dm / 1024, 256>>>(Wq, wq, 2 * Dm * Dm / 4);
    rnd_kernel<<<2 * Dm * Dm / 1024, 256>>>(Wk, wk, 2 * Dm * Dm / 4);
    rnd_kernel<<<2 * Dm * Dm / 1024, 256>>>(Wv, wv, 2 * Dm * Dm / 4);
    rnd_kernel<<<2 * Dm * Dm / 1024, 256>>>(Wo, wo, 2 * Dm * Dm / 4);
    rnd_kernel<<<2 * Dm * DFFm / 1024, 256>>>(ffn_w1, w1, 2 * Dm * DFFm / 4);
    rnd_kernel<<<2 * Dm * DFFm / 1024, 256>>>(ffn_w2, w2, 2 * Dm * DFFm / 4);

    dim3 lnb(32, 8);
    dim3 gemmDD(Dm / TBN, Mpts / TBM);    // (2,128)
    dim3 gemmDF(DFFm / TBN, Mpts / TBM);  // (8,128)

    for (int blk = 0; blk < 2; blk++) {
        const float* xin = (blk == 0) ? feat_a : x;   // residual stream (fp32)
        const float* ctx = (blk == 0) ? fa : fb;      // tf32-rounded context
        const float* cc  = (blk == 0) ? coord_a : coord_b;
        const int* idx   = (blk == 0) ? knn_a2a : knn_a2b;
        size_t woff = (size_t)blk * Dm * Dm;

        ln_kernel<<<Mpts / 8, lnb>>>(xin, ln1_g + blk * Dm, ln1_b + blk * Dm, xn);
        gemm_tf32<0><<<gemmDD, 256, GEMM_SMEM>>>(xn,  wq + woff, nullptr, nullptr, q, Dm, Dm);
        gemm_tf32<0><<<gemmDD, 256, GEMM_SMEM>>>(ctx, wk + woff, nullptr, nullptr, k, Dm, Dm);
        gemm_tf32<0><<<gemmDD, 256, GEMM_SMEM>>>(ctx, wv + woff, nullptr, nullptr, v, Dm, Dm);

        attn_kernel<<<Mpts / 8, 256>>>(q, k, v, coord_a, cc, idx,
                                       pe_w + (size_t)blk * 3 * Dm, pe_b + blk * Dm, attn);

        gemm_tf32<1><<<gemmDD, 256, GEMM_SMEM>>>(attn, wo + woff, nullptr, xin, x, Dm, Dm);

        ln_kernel<<<Mpts / 8, lnb>>>(x, ln2_g + blk * Dm, ln2_b + blk * Dm, xn);
        gemm_tf32<2><<<gemmDF, 256, GEMM_SMEM>>>(xn, w1 + (size_t)blk * Dm * DFFm,
                                                 ffn_b1 + blk * DFFm, nullptr, h, DFFm, Dm);
        float* xo = (blk == 1) ? out : x;
        gemm_tf32<3><<<gemmDD, 256, GEMM_SMEM>>>(h, w2 + (size_t)blk * DFFm * Dm,
                                                 ffn_b2 + blk * Dm, x, xo, Dm, DFFm);
    }
}